// round 3
// baseline (speedup 1.0000x reference)
#include <cuda_runtime.h>
#include <cstdint>

#define N_NODES 100000
#define N_EDGES 1600000
#define D 128
#define K2 256

typedef unsigned long long u64;

// ---------------- scratch (device globals; no allocation allowed) ----------
__device__ int   g_deg[N_NODES];
__device__ int   g_off[N_NODES + 1];
__device__ int   g_cursor[N_NODES];
__device__ int   g_srcs[N_EDGES];
__device__ float g_ahn[(size_t)N_NODES * D];   // normalized aggregated features

// ---------------- packed fp32x2 helpers --------------------------------------
__device__ __forceinline__ void fma2(u64& d, u64 a, u64 b) {
    asm("fma.rn.f32x2 %0, %1, %2, %3;" : "=l"(d) : "l"(a), "l"(b), "l"(d));
}
__device__ __forceinline__ u64 dup2(float x) {
    u64 r;
    asm("mov.b64 %0, {%1, %1};" : "=l"(r) : "r"(__float_as_uint(x)));
    return r;
}
__device__ __forceinline__ void unpack2(float& lo, float& hi, u64 v) {
    uint32_t a, b;
    asm("mov.b64 {%0, %1}, %2;" : "=r"(a), "=r"(b) : "l"(v));
    lo = __uint_as_float(a);
    hi = __uint_as_float(b);
}

// ---------------- small setup kernels ---------------------------------------
__global__ void k_zero_deg() {
    int i = blockIdx.x * blockDim.x + threadIdx.x;
    if (i < N_NODES) g_deg[i] = 0;
}

__global__ void k_count(const int* __restrict__ dst) {
    int e = blockIdx.x * blockDim.x + threadIdx.x;
    if (e < N_EDGES) atomicAdd(&g_deg[dst[e]], 1);
}

// single-block exclusive scan of g_deg -> g_off (and g_cursor copy)
__global__ void k_scan() {
    __shared__ int sums[1024];
    const int n = N_NODES;
    int tid = threadIdx.x;
    const int chunk = (n + 1023) / 1024;
    int base = tid * chunk;
    int s = 0;
    for (int i = 0; i < chunk; i++) {
        int idx = base + i;
        if (idx < n) s += g_deg[idx];
    }
    sums[tid] = s;
    __syncthreads();
    for (int off = 1; off < 1024; off <<= 1) {
        int v = (tid >= off) ? sums[tid - off] : 0;
        __syncthreads();
        sums[tid] += v;
        __syncthreads();
    }
    int run = (tid == 0) ? 0 : sums[tid - 1];
    for (int i = 0; i < chunk; i++) {
        int idx = base + i;
        if (idx < n) {
            g_off[idx] = run;
            g_cursor[idx] = run;
            run += g_deg[idx];
        }
    }
    if (tid == 1023) g_off[n] = sums[1023];
}

__global__ void k_scatter(const int* __restrict__ src, const int* __restrict__ dst) {
    int e = blockIdx.x * blockDim.x + threadIdx.x;
    if (e < N_EDGES) {
        int p = atomicAdd(&g_cursor[dst[e]], 1);
        g_srcs[p] = src[e];
    }
}

// ---------------- aggregation: one warp per dst node ------------------------
__global__ void k_aggregate(const float* __restrict__ h) {
    int warp = (blockIdx.x * blockDim.x + threadIdx.x) >> 5;
    int lane = threadIdx.x & 31;
    if (warp >= N_NODES) return;
    int beg = g_off[warp];
    int end = g_off[warp + 1];
    const float4* h4 = (const float4*)h;
    float4 acc = make_float4(0.f, 0.f, 0.f, 0.f);
    int e = beg;
    int s_next = (e < end) ? g_srcs[e] : 0;
    for (; e < end; ) {
        int s = s_next;
        ++e;
        if (e < end) s_next = g_srcs[e];
        float4 v = __ldg(&h4[(size_t)s * 32 + lane]);
        acc.x += v.x; acc.y += v.y; acc.z += v.z; acc.w += v.w;
    }
    float norm = (end > beg) ? 1.0f / (float)(end - beg) : 0.0f;
    acc.x *= norm; acc.y *= norm; acc.z *= norm; acc.w *= norm;
    ((float4*)g_ahn)[(size_t)warp * 32 + lane] = acc;
}

// ---------------- fused GEMM (cat @ W^T + b) + LayerNorm + ReLU --------------
// Block tile: 128 rows x 128 cols, 256 threads, 8x8 per thread.
// Inner product on packed fma.rn.f32x2 (2 lane-FMAs per issued instruction).
// Full W kept k-major in shared (loaded once per block); A tiles double-buffered.
#define MT 128
#define NT 128
#define KT 32
#define ASTRIDE (MT + 4)   // 132
#define ABUF (KT * ASTRIDE)
#define BSTRIDE (NT + 4)   // 132

__global__ void __launch_bounds__(256, 1)
k_gemm_ln(const float* __restrict__ h,
          const float* __restrict__ W,
          const float* __restrict__ bias,
          const float* __restrict__ gamma,
          const float* __restrict__ beta,
          float* __restrict__ out)
{
    extern __shared__ float smem[];
    float* As = smem;                       // 2 x [KT][ASTRIDE]
    float* Bs = smem + 2 * ABUF;            // [K2][BSTRIDE]

    const int tid = threadIdx.x;
    const int tx = tid & 15;    // n-group: cols tx*8 .. tx*8+7
    const int ty = tid >> 4;    // m-group: rows ty*8 .. ty*8+7 (0..15)
    const int row0 = blockIdx.x * MT;

    // ---- stage full W transposed: Bs[k][n] = W[n][k] ----
    {
        const float4* W4 = (const float4*)W;
#pragma unroll
        for (int q = 0; q < 32; q++) {
            int idx = tid + 256 * q;     // 0..8191
            int n = idx >> 6;
            int kc = idx & 63;
            float4 v = W4[(size_t)n * 64 + kc];
            int kk = kc * 4;
            Bs[(kk + 0) * BSTRIDE + n] = v.x;
            Bs[(kk + 1) * BSTRIDE + n] = v.y;
            Bs[(kk + 2) * BSTRIDE + n] = v.z;
            Bs[(kk + 3) * BSTRIDE + n] = v.w;
        }
    }

    // per-thread column params
    float gam[8], bet[8], bvec[8];
#pragma unroll
    for (int j = 0; j < 8; j++) {
        int c = tx * 8 + j;
        gam[j] = gamma[c];
        bet[j] = beta[c];
        bvec[j] = bias[c];
    }

    u64 acc2[8][4];
#pragma unroll
    for (int i = 0; i < 8; i++)
#pragma unroll
        for (int jp = 0; jp < 4; jp++) acc2[i][jp] = 0ull;

    const float4* h4 = (const float4*)h;
    const float4* a4 = (const float4*)g_ahn;

    const int kc = tid & 7;    // float4 chunk within KT
    const int mb = tid >> 3;   // 0..31

    // preload tile 0
    float4 pre[4];
    {
        const float4* asrc = h4;
#pragma unroll
        for (int q = 0; q < 4; q++) {
            int row = row0 + mb + 32 * q;
            if (row >= N_NODES) row = N_NODES - 1;
            pre[q] = asrc[(size_t)row * 32 + kc];
        }
    }
    // store tile 0 into buffer 0
    {
        int kk = kc * 4;
#pragma unroll
        for (int q = 0; q < 4; q++) {
            int m = mb + 32 * q;
            As[(kk + 0) * ASTRIDE + m] = pre[q].x;
            As[(kk + 1) * ASTRIDE + m] = pre[q].y;
            As[(kk + 2) * ASTRIDE + m] = pre[q].z;
            As[(kk + 3) * ASTRIDE + m] = pre[q].w;
        }
    }
    __syncthreads();

    for (int kb = 0; kb < K2; kb += KT) {
        // prefetch next tile (global loads overlap compute below)
        const bool more = (kb + KT) < K2;
        if (more) {
            int kn = kb + KT;
            const float4* asrc = (kn < D) ? h4 : a4;
            int koff = ((kn < D) ? kn : (kn - D)) >> 2;
#pragma unroll
            for (int q = 0; q < 4; q++) {
                int row = row0 + mb + 32 * q;
                if (row >= N_NODES) row = N_NODES - 1;
                pre[q] = asrc[(size_t)row * 32 + koff + kc];
            }
        }

        const float* Acur = As + ((kb >> 5) & 1) * ABUF;

#pragma unroll 4
        for (int k = 0; k < KT; k++) {
            const float* brow = &Bs[(kb + k) * BSTRIDE + (tx << 3)];
            ulonglong2 bA = *(const ulonglong2*)brow;
            ulonglong2 bB = *(const ulonglong2*)(brow + 4);
            u64 b2[4] = {bA.x, bA.y, bB.x, bB.y};

            const float* arow = &Acur[k * ASTRIDE + (ty << 3)];
            float4 a0 = *(const float4*)arow;
            float4 a1 = *(const float4*)(arow + 4);
            float av[8] = {a0.x, a0.y, a0.z, a0.w, a1.x, a1.y, a1.z, a1.w};
#pragma unroll
            for (int i = 0; i < 8; i++) {
                u64 aa = dup2(av[i]);
#pragma unroll
                for (int jp = 0; jp < 4; jp++)
                    fma2(acc2[i][jp], aa, b2[jp]);
            }
        }

        if (more) {
            float* Anxt = As + (((kb >> 5) + 1) & 1) * ABUF;
            int kk = kc * 4;
#pragma unroll
            for (int q = 0; q < 4; q++) {
                int m = mb + 32 * q;
                Anxt[(kk + 0) * ASTRIDE + m] = pre[q].x;
                Anxt[(kk + 1) * ASTRIDE + m] = pre[q].y;
                Anxt[(kk + 2) * ASTRIDE + m] = pre[q].z;
                Anxt[(kk + 3) * ASTRIDE + m] = pre[q].w;
            }
        }
        __syncthreads();
    }

    // unpack accumulators
    float acc[8][8];
#pragma unroll
    for (int i = 0; i < 8; i++)
#pragma unroll
        for (int jp = 0; jp < 4; jp++)
            unpack2(acc[i][2 * jp], acc[i][2 * jp + 1], acc2[i][jp]);

    // ---- epilogue: bias + LayerNorm + ReLU, row-wise (128 cols over 16 lanes)
#pragma unroll
    for (int i = 0; i < 8; i++) {
        float s = 0.f;
#pragma unroll
        for (int j = 0; j < 8; j++) {
            acc[i][j] += bvec[j];
            s += acc[i][j];
        }
#pragma unroll
        for (int o = 8; o >= 1; o >>= 1)
            s += __shfl_xor_sync(0xffffffffu, s, o);
        float mu = s * (1.0f / 128.0f);

        float vs = 0.f;
#pragma unroll
        for (int j = 0; j < 8; j++) {
            float dlt = acc[i][j] - mu;
            vs += dlt * dlt;
        }
#pragma unroll
        for (int o = 8; o >= 1; o >>= 1)
            vs += __shfl_xor_sync(0xffffffffu, vs, o);
        float inv = rsqrtf(vs * (1.0f / 128.0f) + 1e-5f);

        int row = row0 + ty * 8 + i;
        if (row < N_NODES) {
            float o8[8];
#pragma unroll
            for (int j = 0; j < 8; j++) {
                float v = (acc[i][j] - mu) * inv * gam[j] + bet[j];
                o8[j] = v > 0.f ? v : 0.f;
            }
            float4* dst4 = (float4*)&out[(size_t)row * 128 + tx * 8];
            dst4[0] = make_float4(o8[0], o8[1], o8[2], o8[3]);
            dst4[1] = make_float4(o8[4], o8[5], o8[6], o8[7]);
        }
    }
}

// ---------------- launcher ---------------------------------------------------
extern "C" void kernel_launch(void* const* d_in, const int* in_sizes, int n_in,
                              void* d_out, int out_size) {
    const float* h     = (const float*)d_in[0];
    const float* W     = (const float*)d_in[1];
    const float* b     = (const float*)d_in[2];
    const float* gamma = (const float*)d_in[3];
    const float* beta  = (const float*)d_in[4];
    const int*   src   = (const int*)d_in[5];
    const int*   dst   = (const int*)d_in[6];
    float* out = (float*)d_out;

    k_zero_deg<<<(N_NODES + 255) / 256, 256>>>();
    k_count<<<(N_EDGES + 255) / 256, 256>>>(dst);
    k_scan<<<1, 1024>>>();
    k_scatter<<<(N_EDGES + 255) / 256, 256>>>(src, dst);
    k_aggregate<<<(N_NODES * 32 + 255) / 256, 256>>>(h);

    const size_t SMEM = (size_t)(2 * ABUF + K2 * BSTRIDE) * sizeof(float);
    cudaFuncSetAttribute(k_gemm_ln, cudaFuncAttributeMaxDynamicSharedMemorySize,
                         (int)SMEM);
    k_gemm_ln<<<(N_NODES + MT - 1) / MT, 256, SMEM>>>(h, W, b, gamma, beta, out);
}

// round 4
// speedup vs baseline: 1.0398x; 1.0398x over previous
#include <cuda_runtime.h>
#include <cstdint>

#define N_NODES 100000
#define N_EDGES 1600000
#define D 128
#define K2 256

typedef unsigned long long u64;

// ---------------- scratch (device globals; no allocation allowed) ----------
__device__ int   g_deg[N_NODES];
__device__ int   g_off[N_NODES + 1];
__device__ int   g_cursor[N_NODES];
__device__ int   g_srcs[N_EDGES];
__device__ float g_ahn[(size_t)N_NODES * D];   // normalized aggregated feats
__device__ float g_y[(size_t)N_NODES * D];     // partial GEMM accumulator

// ---------------- packed fp32x2 helpers --------------------------------------
__device__ __forceinline__ void fma2(u64& d, u64 a, u64 b) {
    asm("fma.rn.f32x2 %0, %1, %2, %3;" : "=l"(d) : "l"(a), "l"(b), "l"(d));
}
__device__ __forceinline__ u64 dup2(float x) {
    u64 r;
    asm("mov.b64 %0, {%1, %1};" : "=l"(r) : "r"(__float_as_uint(x)));
    return r;
}
__device__ __forceinline__ void unpack2(float& lo, float& hi, u64 v) {
    uint32_t a, b;
    asm("mov.b64 {%0, %1}, %2;" : "=r"(a), "=r"(b) : "l"(v));
    lo = __uint_as_float(a);
    hi = __uint_as_float(b);
}

// ---------------- small setup kernels ---------------------------------------
__global__ void k_zero_deg() {
    int i = blockIdx.x * blockDim.x + threadIdx.x;
    if (i < N_NODES) g_deg[i] = 0;
}

__global__ void k_count(const int* __restrict__ dst) {
    int e = blockIdx.x * blockDim.x + threadIdx.x;
    if (e < N_EDGES) atomicAdd(&g_deg[dst[e]], 1);
}

__global__ void k_scan() {
    __shared__ int sums[1024];
    const int n = N_NODES;
    int tid = threadIdx.x;
    const int chunk = (n + 1023) / 1024;
    int base = tid * chunk;
    int s = 0;
    for (int i = 0; i < chunk; i++) {
        int idx = base + i;
        if (idx < n) s += g_deg[idx];
    }
    sums[tid] = s;
    __syncthreads();
    for (int off = 1; off < 1024; off <<= 1) {
        int v = (tid >= off) ? sums[tid - off] : 0;
        __syncthreads();
        sums[tid] += v;
        __syncthreads();
    }
    int run = (tid == 0) ? 0 : sums[tid - 1];
    for (int i = 0; i < chunk; i++) {
        int idx = base + i;
        if (idx < n) {
            g_off[idx] = run;
            g_cursor[idx] = run;
            run += g_deg[idx];
        }
    }
    if (tid == 1023) g_off[n] = sums[1023];
}

__global__ void k_scatter(const int* __restrict__ src, const int* __restrict__ dst) {
    int e = blockIdx.x * blockDim.x + threadIdx.x;
    if (e < N_EDGES) {
        int p = atomicAdd(&g_cursor[dst[e]], 1);
        g_srcs[p] = src[e];
    }
}

// ---------------- aggregation: one warp per dst node ------------------------
__global__ void k_aggregate(const float* __restrict__ h) {
    int warp = (blockIdx.x * blockDim.x + threadIdx.x) >> 5;
    int lane = threadIdx.x & 31;
    if (warp >= N_NODES) return;
    int beg = g_off[warp];
    int end = g_off[warp + 1];
    const float4* h4 = (const float4*)h;
    float4 acc = make_float4(0.f, 0.f, 0.f, 0.f);
    int e = beg;
    int s_next = (e < end) ? g_srcs[e] : 0;
    for (; e < end; ) {
        int s = s_next;
        ++e;
        if (e < end) s_next = g_srcs[e];
        float4 v = __ldg(&h4[(size_t)s * 32 + lane]);
        acc.x += v.x; acc.y += v.y; acc.z += v.z; acc.w += v.w;
    }
    float norm = (end > beg) ? 1.0f / (float)(end - beg) : 0.0f;
    acc.x *= norm; acc.y *= norm; acc.z *= norm; acc.w *= norm;
    ((float4*)g_ahn)[(size_t)warp * 32 + lane] = acc;
}

// ---------------- half-K GEMM (K=128), f32x2 inner product -------------------
// PART 0: g_y = A @ W[:, 0:128]^T                (A = h)
// PART 1: out = LN(g_y + A @ W[:,128:256]^T + b) (A = g_ahn) + ReLU
// Tile: 256 rows x 128 cols per CTA, 512 threads, 8x8 per thread,
// double-buffered A tiles (KT=32), W half resident in SMEM.
#define MT 256
#define NT 128
#define KT 32
#define KH 128
#define ASTRIDE (MT + 4)   // 260
#define ABUF (KT * ASTRIDE)
#define BSTRIDE (NT + 4)   // 132
#define GEMM_SMEM ((2 * ABUF + KH * BSTRIDE) * sizeof(float))

template <int PART>
__global__ void __launch_bounds__(512, 1)
k_gemm_half(const float* __restrict__ A,
            const float* __restrict__ W,
            const float* __restrict__ bias,
            const float* __restrict__ gamma,
            const float* __restrict__ beta,
            float* __restrict__ out)
{
    extern __shared__ float smem[];
    float* As = smem;                 // 2 x [KT][ASTRIDE]
    float* Bs = smem + 2 * ABUF;      // [KH][BSTRIDE]

    const int tid = threadIdx.x;
    const int tx = tid & 15;          // col group: tx*8 .. tx*8+7
    const int ty = tid >> 4;          // row group: ty*8 .. ty*8+7 (0..31)
    const int row0 = blockIdx.x * MT;

    // ---- stage W half transposed: Bs[k][n] = W[n][PART*128 + k] ----
    {
        const float4* W4 = (const float4*)W;
#pragma unroll
        for (int q = 0; q < 8; q++) {
            int idx = tid + 512 * q;      // 0..4095
            int n = idx >> 5;             // 0..127
            int kc = idx & 31;            // float4 chunk within the half
            float4 v = W4[(size_t)n * 64 + PART * 32 + kc];
            int kk = kc * 4;
            Bs[(kk + 0) * BSTRIDE + n] = v.x;
            Bs[(kk + 1) * BSTRIDE + n] = v.y;
            Bs[(kk + 2) * BSTRIDE + n] = v.z;
            Bs[(kk + 3) * BSTRIDE + n] = v.w;
        }
    }

    u64 acc2[8][4];
#pragma unroll
    for (int i = 0; i < 8; i++)
#pragma unroll
        for (int jp = 0; jp < 4; jp++) acc2[i][jp] = 0ull;

    const float4* A4 = (const float4*)A;
    const int kc = tid & 7;    // float4 chunk within KT
    const int mb = tid >> 3;   // 0..63

    // preload tile 0
    float4 pre[4];
#pragma unroll
    for (int q = 0; q < 4; q++) {
        int row = row0 + mb + 64 * q;
        if (row >= N_NODES) row = N_NODES - 1;
        pre[q] = A4[(size_t)row * 32 + kc];
    }
    {
        int kk = kc * 4;
#pragma unroll
        for (int q = 0; q < 4; q++) {
            int m = mb + 64 * q;
            As[(kk + 0) * ASTRIDE + m] = pre[q].x;
            As[(kk + 1) * ASTRIDE + m] = pre[q].y;
            As[(kk + 2) * ASTRIDE + m] = pre[q].z;
            As[(kk + 3) * ASTRIDE + m] = pre[q].w;
        }
    }
    __syncthreads();

#pragma unroll
    for (int kb = 0; kb < KH; kb += KT) {
        const bool more = (kb + KT) < KH;
        if (more) {
            int koff = (kb + KT) >> 2;
#pragma unroll
            for (int q = 0; q < 4; q++) {
                int row = row0 + mb + 64 * q;
                if (row >= N_NODES) row = N_NODES - 1;
                pre[q] = A4[(size_t)row * 32 + koff + kc];
            }
        }

        const float* Acur = As + ((kb >> 5) & 1) * ABUF;

#pragma unroll 4
        for (int k = 0; k < KT; k++) {
            const float* brow = &Bs[(kb + k) * BSTRIDE + (tx << 3)];
            ulonglong2 bA = *(const ulonglong2*)brow;
            ulonglong2 bB = *(const ulonglong2*)(brow + 4);
            u64 b2[4] = {bA.x, bA.y, bB.x, bB.y};

            const float* arow = &Acur[k * ASTRIDE + (ty << 3)];
            float4 a0 = *(const float4*)arow;
            float4 a1 = *(const float4*)(arow + 4);
            float av[8] = {a0.x, a0.y, a0.z, a0.w, a1.x, a1.y, a1.z, a1.w};
#pragma unroll
            for (int i = 0; i < 8; i++) {
                u64 aa = dup2(av[i]);
#pragma unroll
                for (int jp = 0; jp < 4; jp++)
                    fma2(acc2[i][jp], aa, b2[jp]);
            }
        }

        if (more) {
            float* Anxt = As + (((kb >> 5) + 1) & 1) * ABUF;
            int kk = kc * 4;
#pragma unroll
            for (int q = 0; q < 4; q++) {
                int m = mb + 64 * q;
                Anxt[(kk + 0) * ASTRIDE + m] = pre[q].x;
                Anxt[(kk + 1) * ASTRIDE + m] = pre[q].y;
                Anxt[(kk + 2) * ASTRIDE + m] = pre[q].z;
                Anxt[(kk + 3) * ASTRIDE + m] = pre[q].w;
            }
        }
        __syncthreads();
    }

    float acc[8][8];
#pragma unroll
    for (int i = 0; i < 8; i++)
#pragma unroll
        for (int jp = 0; jp < 4; jp++)
            unpack2(acc[i][2 * jp], acc[i][2 * jp + 1], acc2[i][jp]);

    if (PART == 0) {
        // store raw partial sums
        float4* y4 = (float4*)g_y;
#pragma unroll
        for (int i = 0; i < 8; i++) {
            int row = row0 + ty * 8 + i;
            if (row < N_NODES) {
                y4[(size_t)row * 32 + tx * 2] =
                    make_float4(acc[i][0], acc[i][1], acc[i][2], acc[i][3]);
                y4[(size_t)row * 32 + tx * 2 + 1] =
                    make_float4(acc[i][4], acc[i][5], acc[i][6], acc[i][7]);
            }
        }
    } else {
        float gam[8], bet[8], bvec[8];
#pragma unroll
        for (int j = 0; j < 8; j++) {
            int c = tx * 8 + j;
            gam[j] = gamma[c];
            bet[j] = beta[c];
            bvec[j] = bias[c];
        }
        const float4* y4 = (const float4*)g_y;
#pragma unroll
        for (int i = 0; i < 8; i++) {
            int row = row0 + ty * 8 + i;
            int rclamp = (row < N_NODES) ? row : (N_NODES - 1);
            float4 y0 = y4[(size_t)rclamp * 32 + tx * 2];
            float4 y1 = y4[(size_t)rclamp * 32 + tx * 2 + 1];
            acc[i][0] += y0.x; acc[i][1] += y0.y; acc[i][2] += y0.z; acc[i][3] += y0.w;
            acc[i][4] += y1.x; acc[i][5] += y1.y; acc[i][6] += y1.z; acc[i][7] += y1.w;

            float s = 0.f;
#pragma unroll
            for (int j = 0; j < 8; j++) {
                acc[i][j] += bvec[j];
                s += acc[i][j];
            }
#pragma unroll
            for (int o = 8; o >= 1; o >>= 1)
                s += __shfl_xor_sync(0xffffffffu, s, o);
            float mu = s * (1.0f / 128.0f);

            float vs = 0.f;
#pragma unroll
            for (int j = 0; j < 8; j++) {
                float dlt = acc[i][j] - mu;
                vs += dlt * dlt;
            }
#pragma unroll
            for (int o = 8; o >= 1; o >>= 1)
                vs += __shfl_xor_sync(0xffffffffu, vs, o);
            float inv = rsqrtf(vs * (1.0f / 128.0f) + 1e-5f);

            if (row < N_NODES) {
                float o8[8];
#pragma unroll
                for (int j = 0; j < 8; j++) {
                    float v = (acc[i][j] - mu) * inv * gam[j] + bet[j];
                    o8[j] = v > 0.f ? v : 0.f;
                }
                float4* dst4 = (float4*)&out[(size_t)row * 128 + tx * 8];
                dst4[0] = make_float4(o8[0], o8[1], o8[2], o8[3]);
                dst4[1] = make_float4(o8[4], o8[5], o8[6], o8[7]);
            }
        }
    }
}

// ---------------- launcher ---------------------------------------------------
extern "C" void kernel_launch(void* const* d_in, const int* in_sizes, int n_in,
                              void* d_out, int out_size) {
    const float* h     = (const float*)d_in[0];
    const float* W     = (const float*)d_in[1];
    const float* b     = (const float*)d_in[2];
    const float* gamma = (const float*)d_in[3];
    const float* beta  = (const float*)d_in[4];
    const int*   src   = (const int*)d_in[5];
    const int*   dst   = (const int*)d_in[6];
    float* out = (float*)d_out;

    static cudaStream_t s2;
    static cudaEvent_t evFork, evP1;
    static float* ahn_ptr = nullptr;
    static int inited = 0;
    if (!inited) {
        cudaStreamCreateWithFlags(&s2, cudaStreamNonBlocking);
        cudaEventCreateWithFlags(&evFork, cudaEventDisableTiming);
        cudaEventCreateWithFlags(&evP1, cudaEventDisableTiming);
        cudaGetSymbolAddress((void**)&ahn_ptr, g_ahn);
        cudaFuncSetAttribute(k_gemm_half<0>,
                             cudaFuncAttributeMaxDynamicSharedMemorySize,
                             (int)GEMM_SMEM);
        cudaFuncSetAttribute(k_gemm_half<1>,
                             cudaFuncAttributeMaxDynamicSharedMemorySize,
                             (int)GEMM_SMEM);
        inited = 1;
    }

    const int GBLK = (N_NODES + MT - 1) / MT;

    // fork: h-half GEMM runs concurrently with CSR build + aggregation
    cudaEventRecord(evFork, 0);
    cudaStreamWaitEvent(s2, evFork, 0);
    k_gemm_half<0><<<GBLK, 512, GEMM_SMEM, s2>>>(h, W, nullptr, nullptr, nullptr,
                                                 nullptr);
    cudaEventRecord(evP1, s2);

    // CSR build + aggregate on the main (capture) stream
    k_zero_deg<<<(N_NODES + 255) / 256, 256>>>();
    k_count<<<(N_EDGES + 255) / 256, 256>>>(dst);
    k_scan<<<1, 1024>>>();
    k_scatter<<<(N_EDGES + 255) / 256, 256>>>(src, dst);
    k_aggregate<<<(N_NODES * 32 + 255) / 256, 256>>>(h);

    // join, then final half-GEMM + bias + LayerNorm + ReLU
    cudaStreamWaitEvent(0, evP1, 0);
    k_gemm_half<1><<<GBLK, 512, GEMM_SMEM>>>(ahn_ptr, W, b, gamma, beta, out);
}

// round 5
// speedup vs baseline: 1.5710x; 1.5108x over previous
#include <cuda_runtime.h>
#include <cstdint>

#define N_NODES 100000
#define N_EDGES 1600000
#define D 128
#define K2 256

#define SCAN_NBLK ((N_NODES + 4095) / 4096)   // 25

typedef unsigned long long u64;

// ---------------- scratch (device globals; no allocation allowed) ----------
__device__ int   g_deg[N_NODES];
__device__ int   g_off[N_NODES + 1];
__device__ int   g_cursor[N_NODES];
__device__ int   g_srcs[N_EDGES];
__device__ int   g_blksum[32];
__device__ int   g_blkoff[32];
__device__ float g_ahn[(size_t)N_NODES * D];   // normalized aggregated feats
__device__ float g_y[(size_t)N_NODES * D];     // partial GEMM accumulator

// ---------------- packed fp32x2 helpers --------------------------------------
__device__ __forceinline__ void fma2(u64& d, u64 a, u64 b) {
    asm("fma.rn.f32x2 %0, %1, %2, %3;" : "=l"(d) : "l"(a), "l"(b), "l"(d));
}
__device__ __forceinline__ u64 dup2(float x) {
    u64 r;
    asm("mov.b64 %0, {%1, %1};" : "=l"(r) : "r"(__float_as_uint(x)));
    return r;
}
__device__ __forceinline__ void unpack2(float& lo, float& hi, u64 v) {
    uint32_t a, b;
    asm("mov.b64 {%0, %1}, %2;" : "=r"(a), "=r"(b) : "l"(v));
    lo = __uint_as_float(a);
    hi = __uint_as_float(b);
}

// ---------------- small setup kernels ---------------------------------------
__global__ void k_zero_deg() {
    int i = blockIdx.x * blockDim.x + threadIdx.x;
    if (i < N_NODES) g_deg[i] = 0;
}

__global__ void k_count(const int* __restrict__ dst) {
    int e = blockIdx.x * blockDim.x + threadIdx.x;
    if (e < N_EDGES) atomicAdd(&g_deg[dst[e]], 1);
}

// ---- 3-kernel exclusive scan of g_deg -> g_off / g_cursor -------------------
__global__ void k_scan1() {
    __shared__ int wsum[32];
    const int b = blockIdx.x, t = threadIdx.x;
    const int lane = t & 31, wid = t >> 5;
    const int base = b * 4096 + t * 4;

    int v0 = 0, v1 = 0, v2 = 0, v3 = 0;
    if (base + 3 < N_NODES) {
        int4 vv = *(const int4*)&g_deg[base];
        v0 = vv.x; v1 = vv.y; v2 = vv.z; v3 = vv.w;
    } else {
        if (base + 0 < N_NODES) v0 = g_deg[base + 0];
        if (base + 1 < N_NODES) v1 = g_deg[base + 1];
        if (base + 2 < N_NODES) v2 = g_deg[base + 2];
        if (base + 3 < N_NODES) v3 = g_deg[base + 3];
    }
    int tsum = v0 + v1 + v2 + v3;

    int x = tsum;
#pragma unroll
    for (int o = 1; o < 32; o <<= 1) {
        int y = __shfl_up_sync(0xffffffffu, x, o);
        if (lane >= o) x += y;
    }
    if (lane == 31) wsum[wid] = x;
    __syncthreads();
    if (wid == 0) {
        int w = wsum[lane];
        int xx = w;
#pragma unroll
        for (int o = 1; o < 32; o <<= 1) {
            int y = __shfl_up_sync(0xffffffffu, xx, o);
            if (lane >= o) xx += y;
        }
        wsum[lane] = xx - w;          // exclusive warp offset
        if (lane == 31) g_blksum[b] = xx;
    }
    __syncthreads();

    int prefix = wsum[wid] + (x - tsum);   // exclusive prefix within block
    if (base + 3 < N_NODES) {
        *(int4*)&g_off[base] = make_int4(prefix, prefix + v0,
                                         prefix + v0 + v1, prefix + v0 + v1 + v2);
    } else {
        if (base + 0 < N_NODES) g_off[base + 0] = prefix;
        if (base + 1 < N_NODES) g_off[base + 1] = prefix + v0;
        if (base + 2 < N_NODES) g_off[base + 2] = prefix + v0 + v1;
        if (base + 3 < N_NODES) g_off[base + 3] = prefix + v0 + v1 + v2;
    }
}

__global__ void k_scan2() {
    int t = threadIdx.x;   // 32 threads
    int v = (t < SCAN_NBLK) ? g_blksum[t] : 0;
    int x = v;
#pragma unroll
    for (int o = 1; o < 32; o <<= 1) {
        int y = __shfl_up_sync(0xffffffffu, x, o);
        if (t >= o) x += y;
    }
    if (t < SCAN_NBLK) g_blkoff[t] = x - v;
}

__global__ void k_scan3() {
    const int b = blockIdx.x, t = threadIdx.x;
    const int off = g_blkoff[b];
    const int base = b * 4096 + t * 4;
    if (base + 3 < N_NODES) {
        int4 vv = *(const int4*)&g_off[base];
        vv.x += off; vv.y += off; vv.z += off; vv.w += off;
        *(int4*)&g_off[base] = vv;
        *(int4*)&g_cursor[base] = vv;
    } else {
#pragma unroll
        for (int j = 0; j < 4; j++) {
            int idx = base + j;
            if (idx < N_NODES) {
                int val = g_off[idx] + off;
                g_off[idx] = val;
                g_cursor[idx] = val;
            }
        }
    }
    if (b == 0 && t == 0) g_off[N_NODES] = N_EDGES;
}

__global__ void k_scatter(const int* __restrict__ src, const int* __restrict__ dst) {
    int e = blockIdx.x * blockDim.x + threadIdx.x;
    if (e < N_EDGES) {
        int p = atomicAdd(&g_cursor[dst[e]], 1);
        g_srcs[p] = src[e];
    }
}

// ---------------- aggregation: one warp per dst node ------------------------
__global__ void k_aggregate(const float* __restrict__ h) {
    int warp = (blockIdx.x * blockDim.x + threadIdx.x) >> 5;
    int lane = threadIdx.x & 31;
    if (warp >= N_NODES) return;
    int beg = g_off[warp];
    int end = g_off[warp + 1];
    const float4* h4 = (const float4*)h;
    float4 acc = make_float4(0.f, 0.f, 0.f, 0.f);
    int e = beg;
    int s_next = (e < end) ? g_srcs[e] : 0;
    for (; e < end; ) {
        int s = s_next;
        ++e;
        if (e < end) s_next = g_srcs[e];
        float4 v = __ldg(&h4[(size_t)s * 32 + lane]);
        acc.x += v.x; acc.y += v.y; acc.z += v.z; acc.w += v.w;
    }
    float norm = (end > beg) ? 1.0f / (float)(end - beg) : 0.0f;
    acc.x *= norm; acc.y *= norm; acc.z *= norm; acc.w *= norm;
    ((float4*)g_ahn)[(size_t)warp * 32 + lane] = acc;
}

// ---------------- half-K GEMM (K=128), f32x2 inner product -------------------
// PART 0: g_y = A @ W[:, 0:128]^T                (A = h)
// PART 1: out = LN(g_y + A @ W[:,128:256]^T + b) (A = g_ahn) + ReLU
#define MT 256
#define NT 128
#define KT 32
#define KH 128
#define ASTRIDE (MT + 4)   // 260
#define ABUF (KT * ASTRIDE)
#define BSTRIDE (NT + 4)   // 132
#define GEMM_SMEM ((2 * ABUF + KH * BSTRIDE) * sizeof(float))

template <int PART>
__global__ void __launch_bounds__(512, 1)
k_gemm_half(const float* __restrict__ A,
            const float* __restrict__ W,
            const float* __restrict__ bias,
            const float* __restrict__ gamma,
            const float* __restrict__ beta,
            float* __restrict__ out)
{
    extern __shared__ float smem[];
    float* As = smem;                 // 2 x [KT][ASTRIDE]
    float* Bs = smem + 2 * ABUF;      // [KH][BSTRIDE]

    const int tid = threadIdx.x;
    const int tx = tid & 15;
    const int ty = tid >> 4;
    const int row0 = blockIdx.x * MT;

    // stage W half transposed: Bs[k][n] = W[n][PART*128 + k]
    {
        const float4* W4 = (const float4*)W;
#pragma unroll
        for (int q = 0; q < 8; q++) {
            int idx = tid + 512 * q;
            int n = idx >> 5;
            int kc = idx & 31;
            float4 v = W4[(size_t)n * 64 + PART * 32 + kc];
            int kk = kc * 4;
            Bs[(kk + 0) * BSTRIDE + n] = v.x;
            Bs[(kk + 1) * BSTRIDE + n] = v.y;
            Bs[(kk + 2) * BSTRIDE + n] = v.z;
            Bs[(kk + 3) * BSTRIDE + n] = v.w;
        }
    }

    u64 acc2[8][4];
#pragma unroll
    for (int i = 0; i < 8; i++)
#pragma unroll
        for (int jp = 0; jp < 4; jp++) acc2[i][jp] = 0ull;

    const float4* A4 = (const float4*)A;
    const int kc = tid & 7;
    const int mb = tid >> 3;

    float4 pre[4];
#pragma unroll
    for (int q = 0; q < 4; q++) {
        int row = row0 + mb + 64 * q;
        if (row >= N_NODES) row = N_NODES - 1;
        pre[q] = A4[(size_t)row * 32 + kc];
    }
    {
        int kk = kc * 4;
#pragma unroll
        for (int q = 0; q < 4; q++) {
            int m = mb + 64 * q;
            As[(kk + 0) * ASTRIDE + m] = pre[q].x;
            As[(kk + 1) * ASTRIDE + m] = pre[q].y;
            As[(kk + 2) * ASTRIDE + m] = pre[q].z;
            As[(kk + 3) * ASTRIDE + m] = pre[q].w;
        }
    }
    __syncthreads();

#pragma unroll
    for (int kb = 0; kb < KH; kb += KT) {
        const bool more = (kb + KT) < KH;
        if (more) {
            int koff = (kb + KT) >> 2;
#pragma unroll
            for (int q = 0; q < 4; q++) {
                int row = row0 + mb + 64 * q;
                if (row >= N_NODES) row = N_NODES - 1;
                pre[q] = A4[(size_t)row * 32 + koff + kc];
            }
        }

        const float* Acur = As + ((kb >> 5) & 1) * ABUF;

#pragma unroll 4
        for (int k = 0; k < KT; k++) {
            const float* brow = &Bs[(kb + k) * BSTRIDE + (tx << 3)];
            ulonglong2 bA = *(const ulonglong2*)brow;
            ulonglong2 bB = *(const ulonglong2*)(brow + 4);
            u64 b2[4] = {bA.x, bA.y, bB.x, bB.y};

            const float* arow = &Acur[k * ASTRIDE + (ty << 3)];
            float4 a0 = *(const float4*)arow;
            float4 a1 = *(const float4*)(arow + 4);
            float av[8] = {a0.x, a0.y, a0.z, a0.w, a1.x, a1.y, a1.z, a1.w};
#pragma unroll
            for (int i = 0; i < 8; i++) {
                u64 aa = dup2(av[i]);
#pragma unroll
                for (int jp = 0; jp < 4; jp++)
                    fma2(acc2[i][jp], aa, b2[jp]);
            }
        }

        if (more) {
            float* Anxt = As + (((kb >> 5) + 1) & 1) * ABUF;
            int kk = kc * 4;
#pragma unroll
            for (int q = 0; q < 4; q++) {
                int m = mb + 64 * q;
                Anxt[(kk + 0) * ASTRIDE + m] = pre[q].x;
                Anxt[(kk + 1) * ASTRIDE + m] = pre[q].y;
                Anxt[(kk + 2) * ASTRIDE + m] = pre[q].z;
                Anxt[(kk + 3) * ASTRIDE + m] = pre[q].w;
            }
        }
        __syncthreads();
    }

    float acc[8][8];
#pragma unroll
    for (int i = 0; i < 8; i++)
#pragma unroll
        for (int jp = 0; jp < 4; jp++)
            unpack2(acc[i][2 * jp], acc[i][2 * jp + 1], acc2[i][jp]);

    if (PART == 0) {
        float4* y4 = (float4*)g_y;
#pragma unroll
        for (int i = 0; i < 8; i++) {
            int row = row0 + ty * 8 + i;
            if (row < N_NODES) {
                y4[(size_t)row * 32 + tx * 2] =
                    make_float4(acc[i][0], acc[i][1], acc[i][2], acc[i][3]);
                y4[(size_t)row * 32 + tx * 2 + 1] =
                    make_float4(acc[i][4], acc[i][5], acc[i][6], acc[i][7]);
            }
        }
    } else {
        float gam[8], bet[8], bvec[8];
#pragma unroll
        for (int j = 0; j < 8; j++) {
            int c = tx * 8 + j;
            gam[j] = gamma[c];
            bet[j] = beta[c];
            bvec[j] = bias[c];
        }
        const float4* y4 = (const float4*)g_y;
#pragma unroll
        for (int i = 0; i < 8; i++) {
            int row = row0 + ty * 8 + i;
            int rclamp = (row < N_NODES) ? row : (N_NODES - 1);
            float4 y0 = y4[(size_t)rclamp * 32 + tx * 2];
            float4 y1 = y4[(size_t)rclamp * 32 + tx * 2 + 1];
            acc[i][0] += y0.x; acc[i][1] += y0.y; acc[i][2] += y0.z; acc[i][3] += y0.w;
            acc[i][4] += y1.x; acc[i][5] += y1.y; acc[i][6] += y1.z; acc[i][7] += y1.w;

            float s = 0.f;
#pragma unroll
            for (int j = 0; j < 8; j++) {
                acc[i][j] += bvec[j];
                s += acc[i][j];
            }
#pragma unroll
            for (int o = 8; o >= 1; o >>= 1)
                s += __shfl_xor_sync(0xffffffffu, s, o);
            float mu = s * (1.0f / 128.0f);

            float vs = 0.f;
#pragma unroll
            for (int j = 0; j < 8; j++) {
                float dlt = acc[i][j] - mu;
                vs += dlt * dlt;
            }
#pragma unroll
            for (int o = 8; o >= 1; o >>= 1)
                vs += __shfl_xor_sync(0xffffffffu, vs, o);
            float inv = rsqrtf(vs * (1.0f / 128.0f) + 1e-5f);

            if (row < N_NODES) {
                float o8[8];
#pragma unroll
                for (int j = 0; j < 8; j++) {
                    float v = (acc[i][j] - mu) * inv * gam[j] + bet[j];
                    o8[j] = v > 0.f ? v : 0.f;
                }
                float4* dst4 = (float4*)&out[(size_t)row * 128 + tx * 8];
                dst4[0] = make_float4(o8[0], o8[1], o8[2], o8[3]);
                dst4[1] = make_float4(o8[4], o8[5], o8[6], o8[7]);
            }
        }
    }
}

// ---------------- launcher ---------------------------------------------------
extern "C" void kernel_launch(void* const* d_in, const int* in_sizes, int n_in,
                              void* d_out, int out_size) {
    const float* h     = (const float*)d_in[0];
    const float* W     = (const float*)d_in[1];
    const float* b     = (const float*)d_in[2];
    const float* gamma = (const float*)d_in[3];
    const float* beta  = (const float*)d_in[4];
    const int*   src   = (const int*)d_in[5];
    const int*   dst   = (const int*)d_in[6];
    float* out = (float*)d_out;

    static cudaStream_t s2;
    static cudaEvent_t evFork, evP1;
    static float* ahn_ptr = nullptr;
    static int inited = 0;
    if (!inited) {
        cudaStreamCreateWithFlags(&s2, cudaStreamNonBlocking);
        cudaEventCreateWithFlags(&evFork, cudaEventDisableTiming);
        cudaEventCreateWithFlags(&evP1, cudaEventDisableTiming);
        cudaGetSymbolAddress((void**)&ahn_ptr, g_ahn);
        cudaFuncSetAttribute(k_gemm_half<0>,
                             cudaFuncAttributeMaxDynamicSharedMemorySize,
                             (int)GEMM_SMEM);
        cudaFuncSetAttribute(k_gemm_half<1>,
                             cudaFuncAttributeMaxDynamicSharedMemorySize,
                             (int)GEMM_SMEM);
        inited = 1;
    }

    const int GBLK = (N_NODES + MT - 1) / MT;

    // fork: h-half GEMM runs concurrently with CSR build + aggregation
    cudaEventRecord(evFork, 0);
    cudaStreamWaitEvent(s2, evFork, 0);
    k_gemm_half<0><<<GBLK, 512, GEMM_SMEM, s2>>>(h, W, nullptr, nullptr, nullptr,
                                                 nullptr);
    cudaEventRecord(evP1, s2);

    // CSR build + aggregate on the main (capture) stream
    k_zero_deg<<<(N_NODES + 255) / 256, 256>>>();
    k_count<<<(N_EDGES + 255) / 256, 256>>>(dst);
    k_scan1<<<SCAN_NBLK, 1024>>>();
    k_scan2<<<1, 32>>>();
    k_scan3<<<SCAN_NBLK, 1024>>>();
    k_scatter<<<(N_EDGES + 255) / 256, 256>>>(src, dst);
    k_aggregate<<<(N_NODES * 32 + 255) / 256, 256>>>(h);

    // join, then final half-GEMM + bias + LayerNorm + ReLU
    cudaStreamWaitEvent(0, evP1, 0);
    k_gemm_half<1><<<GBLK, 512, GEMM_SMEM>>>(ahn_ptr, W, b, gamma, beta, out);
}